// round 1
// baseline (speedup 1.0000x reference)
#include <cuda_runtime.h>
#include <math.h>

// Problem constants
#define BATCH 4
#define SEQ   2048
#define DIM   512
#define WIN   64
#define QT    64      // queries per attention block
#define TPAD  65      // padded row width for x tile (bank-conflict avoidance)
#define APAD  65      // padded row width for alpha

// GEMM tiling
#define BM 128
#define BN 64
#define BK 16
#define ASPAD 132     // padded A-tile row (keeps float4 alignment: 132*4 % 16 == 0)

// Context scratch: [B*S, D] fp32 = 16 MB. Device global (no cudaMalloc allowed).
__device__ float g_c[BATCH * SEQ * DIM];

extern __shared__ float sm_dyn[];

// ---------------------------------------------------------------------------
// Attention: per block, 64 queries. Window for query s is positions s-64..s-1
// (strictly causal). Zero-padded rows (global row < 0) give score exactly 0
// and are INCLUDED in the softmax, matching the reference's TF-style padding.
// ---------------------------------------------------------------------------
__global__ void attn_kernel(const float* __restrict__ x) {
    float* tile  = sm_dyn;                 // [128][TPAD] rows qs-64 .. qs+63
    float* alpha = sm_dyn + 128 * TPAD;    // [64][APAD]

    const int tid = threadIdx.x;
    const int tx  = tid & 15;              // phase1: w-group / phase3: d-group
    const int ty  = tid >> 4;              // i-group
    const int b   = blockIdx.x >> 5;       // 32 query tiles per batch
    const int qs  = (blockIdx.x & 31) * QT;
    const float* xb = x + (size_t)b * SEQ * DIM;

    float acc[4][4];
#pragma unroll
    for (int a = 0; a < 4; a++)
#pragma unroll
        for (int c = 0; c < 4; c++) acc[a][c] = 0.f;

    // ---------- Phase 1: scores[i][w] = <x[qs+i], x[qs+i-64+w]> ----------
    for (int ch = 0; ch < DIM / 64; ch++) {
        const int d0 = ch * 64;
        __syncthreads();
        // Load 128 rows x 64 cols of x into smem (zero rows before sequence start)
#pragma unroll
        for (int p = 0; p < 8; p++) {
            int r  = (tid >> 4) + 16 * p;
            int c4 = (tid & 15) * 4;
            int gr = qs - WIN + r;
            float4 v = make_float4(0.f, 0.f, 0.f, 0.f);
            if (gr >= 0)
                v = *reinterpret_cast<const float4*>(xb + (size_t)gr * DIM + d0 + c4);
            float* dst = tile + r * TPAD + c4;
            dst[0] = v.x; dst[1] = v.y; dst[2] = v.z; dst[3] = v.w;
        }
        __syncthreads();
        // Banded product: query local row = 64+i, key local row = i+w
#pragma unroll 4
        for (int d = 0; d < 64; d++) {
            float q[4];
#pragma unroll
            for (int i4 = 0; i4 < 4; i4++)
                q[i4] = tile[(WIN + ty + 16 * i4) * TPAD + d];
#pragma unroll
            for (int i4 = 0; i4 < 4; i4++) {
                const int rb = ty + 16 * i4 + 4 * tx;   // i + 4*tx
#pragma unroll
                for (int w4 = 0; w4 < 4; w4++)
                    acc[i4][w4] = fmaf(q[i4], tile[(rb + w4) * TPAD + d], acc[i4][w4]);
            }
        }
    }

    // ---------- Phase 2: softmax over w (rows owned by 16-lane groups) ----------
#pragma unroll
    for (int i4 = 0; i4 < 4; i4++) {
        float m = fmaxf(fmaxf(acc[i4][0], acc[i4][1]), fmaxf(acc[i4][2], acc[i4][3]));
#pragma unroll
        for (int o = 8; o >= 1; o >>= 1)
            m = fmaxf(m, __shfl_xor_sync(0xffffffffu, m, o));
        float e[4]; float s = 0.f;
#pragma unroll
        for (int w4 = 0; w4 < 4; w4++) { e[w4] = __expf(acc[i4][w4] - m); s += e[w4]; }
#pragma unroll
        for (int o = 8; o >= 1; o >>= 1)
            s += __shfl_xor_sync(0xffffffffu, s, o);
        const float inv = 1.f / s;
        const int i = ty + 16 * i4;
#pragma unroll
        for (int w4 = 0; w4 < 4; w4++)
            alpha[i * APAD + 4 * tx + w4] = e[w4] * inv;
    }

    // ---------- Phase 3: context c[i][d] = sum_w alpha[i][w] * key[i+w][d] ----------
    for (int ch = 0; ch < DIM / 64; ch++) {
        const int d0 = ch * 64;
        __syncthreads();   // also covers alpha visibility on first iteration
#pragma unroll
        for (int p = 0; p < 8; p++) {
            int r  = (tid >> 4) + 16 * p;
            int c4 = (tid & 15) * 4;
            int gr = qs - WIN + r;
            float4 v = make_float4(0.f, 0.f, 0.f, 0.f);
            if (gr >= 0)
                v = *reinterpret_cast<const float4*>(xb + (size_t)gr * DIM + d0 + c4);
            float* dst = tile + r * TPAD + c4;
            dst[0] = v.x; dst[1] = v.y; dst[2] = v.z; dst[3] = v.w;
        }
        __syncthreads();

        float cacc[4][4];
#pragma unroll
        for (int a = 0; a < 4; a++)
#pragma unroll
            for (int c = 0; c < 4; c++) cacc[a][c] = 0.f;

#pragma unroll 4
        for (int w = 0; w < 64; w++) {
#pragma unroll
            for (int i4 = 0; i4 < 4; i4++) {
                const float al = alpha[(ty + 16 * i4) * APAD + w];
                const float* trow = tile + (ty + 16 * i4 + w) * TPAD + 4 * tx;
#pragma unroll
                for (int d4 = 0; d4 < 4; d4++)
                    cacc[i4][d4] = fmaf(al, trow[d4], cacc[i4][d4]);
            }
        }
#pragma unroll
        for (int i4 = 0; i4 < 4; i4++) {
            const size_t m = (size_t)b * SEQ + qs + ty + 16 * i4;
            float4 v = make_float4(cacc[i4][0], cacc[i4][1], cacc[i4][2], cacc[i4][3]);
            *reinterpret_cast<float4*>(g_c + m * DIM + d0 + 4 * tx) = v;
        }
    }
}

// ---------------------------------------------------------------------------
// Output head: out[m][o] = sigmoid( sum_{k<512} c[m][k]*Wc[k][o]
//                                 + sum_{k>=512} x[m][k-512]*Wc[k][o] )
// M=8192, N=512, K=1024. fp32 SIMT, 128x64x16 tiles, 8x4 per thread.
// ---------------------------------------------------------------------------
__global__ void gemm_kernel(const float* __restrict__ x,
                            const float* __restrict__ Wc,
                            float* __restrict__ out) {
    __shared__ float As[BK * ASPAD];   // transposed A tile: As[k][m]
    __shared__ float Bs[BK * BN];      // Bs[k][n]

    const int tid = threadIdx.x;
    const int tx  = tid & 15;          // n-group: n = 4*tx .. 4*tx+3
    const int ty  = tid >> 4;          // m-group: m = 8*ty .. 8*ty+7
    const int bm  = blockIdx.y * BM;
    const int bn  = blockIdx.x * BN;

    float acc[8][4];
#pragma unroll
    for (int j = 0; j < 8; j++)
#pragma unroll
        for (int n = 0; n < 4; n++) acc[j][n] = 0.f;

    for (int kb = 0; kb < 1024 / BK; kb++) {
        const float* Asrc = (kb < 32) ? g_c : x;          // virtual concat [c | x]
        const int koff    = (kb < 32) ? kb * BK : kb * BK - 512;
        __syncthreads();
        {
            // A: 128 rows x 16 k, transposed into As[k][m]
            const int kk4 = (tid & 3) * 4;
            const int m   = tid >> 2;                      // 0..63
#pragma unroll
            for (int p = 0; p < 2; p++) {
                const int mm = m + 64 * p;
                float4 v = *reinterpret_cast<const float4*>(
                    Asrc + (size_t)(bm + mm) * DIM + koff + kk4);
                As[(kk4 + 0) * ASPAD + mm] = v.x;
                As[(kk4 + 1) * ASPAD + mm] = v.y;
                As[(kk4 + 2) * ASPAD + mm] = v.z;
                As[(kk4 + 3) * ASPAD + mm] = v.w;
            }
            // B: 16 k x 64 n
            const int kk = tid >> 4;
            const int n4 = (tid & 15) * 4;
            float4 w = *reinterpret_cast<const float4*>(
                Wc + (size_t)(kb * BK + kk) * DIM + bn + n4);
            *reinterpret_cast<float4*>(Bs + kk * BN + n4) = w;
        }
        __syncthreads();
#pragma unroll
        for (int kk = 0; kk < BK; kk++) {
            float4 a0 = *reinterpret_cast<const float4*>(As + kk * ASPAD + ty * 8);
            float4 a1 = *reinterpret_cast<const float4*>(As + kk * ASPAD + ty * 8 + 4);
            float4 bv = *reinterpret_cast<const float4*>(Bs + kk * BN + tx * 4);
            float a[8] = {a0.x, a0.y, a0.z, a0.w, a1.x, a1.y, a1.z, a1.w};
            float bb[4] = {bv.x, bv.y, bv.z, bv.w};
#pragma unroll
            for (int j = 0; j < 8; j++)
#pragma unroll
                for (int n = 0; n < 4; n++)
                    acc[j][n] = fmaf(a[j], bb[n], acc[j][n]);
        }
    }

    // Epilogue: sigmoid + store
#pragma unroll
    for (int j = 0; j < 8; j++) {
        const size_t m = (size_t)bm + ty * 8 + j;
        float4 o;
        o.x = 1.f / (1.f + __expf(-acc[j][0]));
        o.y = 1.f / (1.f + __expf(-acc[j][1]));
        o.z = 1.f / (1.f + __expf(-acc[j][2]));
        o.w = 1.f / (1.f + __expf(-acc[j][3]));
        *reinterpret_cast<float4*>(out + m * DIM + bn + tx * 4) = o;
    }
}

extern "C" void kernel_launch(void* const* d_in, const int* in_sizes, int n_in,
                              void* d_out, int out_size) {
    const float* x  = (const float*)d_in[0];   // (4, 2048, 512) fp32
    const float* Wc = (const float*)d_in[1];   // (1024, 512) fp32
    float* out = (float*)d_out;                // (4, 2048, 512) fp32

    const size_t attn_smem = (size_t)(128 * TPAD + 64 * APAD) * sizeof(float); // 49,920 B
    cudaFuncSetAttribute(attn_kernel, cudaFuncAttributeMaxDynamicSharedMemorySize,
                         (int)attn_smem);

    attn_kernel<<<BATCH * (SEQ / QT), 256, attn_smem>>>(x);

    dim3 grid(DIM / BN, (BATCH * SEQ) / BM);   // (8, 64)
    gemm_kernel<<<grid, 256>>>(x, Wc, out);
}

// round 3
// speedup vs baseline: 1.7393x; 1.7393x over previous
#include <cuda_runtime.h>
#include <cstdint>
#include <math.h>

// ---------------- problem constants ----------------
#define BATCH 4
#define SEQ   2048
#define DIM   512
#define WIN   64

// attention tiling
#define QT    32
#define TROWS (WIN + QT)   // 96
#define TPAD  65
#define APAD  65

// gemm tiling (mma.sync tf32 m16n8k8)
#define GM 128
#define GN 128
#define KC 32
#define NCHUNK (1024 / KC)     // 32
#define APADW 36               // A smem row pitch (floats) -> conflict-free frag reads
#define BPADW 132              // B smem row pitch (floats)
#define AFLOATS (GM * APADW)           // 4608
#define BFLOATS (KC * BPADW)           // 4224
#define STAGEF  (AFLOATS + BFLOATS)    // 8832 floats per stage

// context scratch [B*S, D] fp32 (no cudaMalloc allowed)
__device__ float g_c[BATCH * SEQ * DIM];

extern __shared__ float sm_dyn[];

// ---------------------------------------------------------------------------
// Attention (QT=32): 256 CTAs. Window = strictly-causal left 64 positions,
// zero-padded head rows included in softmax (score exactly 0), matching ref.
// ---------------------------------------------------------------------------
__global__ void attn_kernel(const float* __restrict__ x) {
    float* tile  = sm_dyn;                  // [96][TPAD]
    float* alpha = sm_dyn + TROWS * TPAD;   // [32][APAD]

    const int tid = threadIdx.x;
    const int tx  = tid & 15;
    const int ty  = tid >> 4;
    const int b   = blockIdx.x >> 6;            // 64 tiles per batch
    const int qs  = (blockIdx.x & 63) * QT;
    const float* xb = x + (size_t)b * SEQ * DIM;

    float acc[2][4];
#pragma unroll
    for (int a = 0; a < 2; a++)
#pragma unroll
        for (int c = 0; c < 4; c++) acc[a][c] = 0.f;

    // Phase 1: scores[i][w] = <x[qs+i], x[qs+i-64+w]>
    for (int ch = 0; ch < DIM / 64; ch++) {
        const int d0 = ch * 64;
        __syncthreads();
#pragma unroll
        for (int p = 0; p < 6; p++) {
            int r  = (tid >> 4) + 16 * p;
            int c4 = (tid & 15) * 4;
            int gr = qs - WIN + r;
            float4 v = make_float4(0.f, 0.f, 0.f, 0.f);
            if (gr >= 0)
                v = *reinterpret_cast<const float4*>(xb + (size_t)gr * DIM + d0 + c4);
            float* dst = tile + r * TPAD + c4;
            dst[0] = v.x; dst[1] = v.y; dst[2] = v.z; dst[3] = v.w;
        }
        __syncthreads();
#pragma unroll 4
        for (int d = 0; d < 64; d++) {
            float q[2];
#pragma unroll
            for (int i4 = 0; i4 < 2; i4++)
                q[i4] = tile[(WIN + ty + 16 * i4) * TPAD + d];
#pragma unroll
            for (int i4 = 0; i4 < 2; i4++) {
                const int rb = ty + 16 * i4 + 4 * tx;
#pragma unroll
                for (int w4 = 0; w4 < 4; w4++)
                    acc[i4][w4] = fmaf(q[i4], tile[(rb + w4) * TPAD + d], acc[i4][w4]);
            }
        }
    }

    // Phase 2: softmax over w (16-lane groups own one query each)
#pragma unroll
    for (int i4 = 0; i4 < 2; i4++) {
        float m = fmaxf(fmaxf(acc[i4][0], acc[i4][1]), fmaxf(acc[i4][2], acc[i4][3]));
#pragma unroll
        for (int o = 8; o >= 1; o >>= 1)
            m = fmaxf(m, __shfl_xor_sync(0xffffffffu, m, o));
        float e[4]; float s = 0.f;
#pragma unroll
        for (int w4 = 0; w4 < 4; w4++) { e[w4] = __expf(acc[i4][w4] - m); s += e[w4]; }
#pragma unroll
        for (int o = 8; o >= 1; o >>= 1)
            s += __shfl_xor_sync(0xffffffffu, s, o);
        const float inv = 1.f / s;
        const int i = ty + 16 * i4;
#pragma unroll
        for (int w4 = 0; w4 < 4; w4++)
            alpha[i * APAD + 4 * tx + w4] = e[w4] * inv;
    }

    // Phase 3: context c[i][d] = sum_w alpha[i][w] * key[i+w][d]
    for (int ch = 0; ch < DIM / 64; ch++) {
        const int d0 = ch * 64;
        __syncthreads();
#pragma unroll
        for (int p = 0; p < 6; p++) {
            int r  = (tid >> 4) + 16 * p;
            int c4 = (tid & 15) * 4;
            int gr = qs - WIN + r;
            float4 v = make_float4(0.f, 0.f, 0.f, 0.f);
            if (gr >= 0)
                v = *reinterpret_cast<const float4*>(xb + (size_t)gr * DIM + d0 + c4);
            float* dst = tile + r * TPAD + c4;
            dst[0] = v.x; dst[1] = v.y; dst[2] = v.z; dst[3] = v.w;
        }
        __syncthreads();

        float cacc[2][4];
#pragma unroll
        for (int a = 0; a < 2; a++)
#pragma unroll
            for (int c = 0; c < 4; c++) cacc[a][c] = 0.f;

#pragma unroll 4
        for (int w = 0; w < 64; w++) {
#pragma unroll
            for (int i4 = 0; i4 < 2; i4++) {
                const float al = alpha[(ty + 16 * i4) * APAD + w];
                const float* trow = tile + (ty + 16 * i4 + w) * TPAD + 4 * tx;
#pragma unroll
                for (int d4 = 0; d4 < 4; d4++)
                    cacc[i4][d4] = fmaf(al, trow[d4], cacc[i4][d4]);
            }
        }
#pragma unroll
        for (int i4 = 0; i4 < 2; i4++) {
            const size_t m = (size_t)b * SEQ + qs + ty + 16 * i4;
            float4 v = make_float4(cacc[i4][0], cacc[i4][1], cacc[i4][2], cacc[i4][3]);
            *reinterpret_cast<float4*>(g_c + m * DIM + d0 + 4 * tx) = v;
        }
    }
}

// ---------------------------------------------------------------------------
// Output head: out = sigmoid([c | x] @ Wc) via mma.sync tf32 m16n8k8.
// M=8192, N=512, K=1024. CTA 128x128, 512 threads (4x4 warps, warp 32x32),
// K-chunks of 32, double-buffered SMEM, LDG->reg prefetch under compute.
// ---------------------------------------------------------------------------
__device__ __forceinline__ void mma_tf32(float* c, uint32_t a0, uint32_t a1,
                                         uint32_t a2, uint32_t a3,
                                         uint32_t b0, uint32_t b1) {
    asm volatile(
        "mma.sync.aligned.m16n8k8.row.col.f32.tf32.tf32.f32 "
        "{%0,%1,%2,%3}, {%4,%5,%6,%7}, {%8,%9}, {%0,%1,%2,%3};"
        : "+f"(c[0]), "+f"(c[1]), "+f"(c[2]), "+f"(c[3])
        : "r"(a0), "r"(a1), "r"(a2), "r"(a3), "r"(b0), "r"(b1));
}

__global__ __launch_bounds__(512) void gemm_mma(const float* __restrict__ x,
                                                const float* __restrict__ Wc,
                                                float* __restrict__ out) {
    const int tid = threadIdx.x;
    const int wid = tid >> 5;
    const int lane = tid & 31;
    const int gid = lane >> 2;          // group id (0..7)
    const int tig = lane & 3;           // thread in group
    const int wm = wid & 3;             // warp M index (0..3)
    const int wn = wid >> 2;            // warp N index (0..3)
    const int bm = blockIdx.y * GM;
    const int bn = blockIdx.x * GN;

    float acc[2][4][4];
#pragma unroll
    for (int i = 0; i < 2; i++)
#pragma unroll
        for (int j = 0; j < 4; j++)
#pragma unroll
            for (int k = 0; k < 4; k++) acc[i][j][k] = 0.f;

    // per-thread load coordinates (fixed across chunks)
    const int ar0 = tid >> 3;            // A rows: idx>>3 for idx=tid, tid+512
    const int aseg = tid & 7;            // A col segment (seg*4)
    const int bk0 = tid >> 5;            // B rows: idx>>5
    const int bn4 = (tid & 31) * 4;      // B col (float4)

    // ---- prologue: load chunk 0 directly to stage 0 ----
    {
        const float* Asrc = g_c;         // chunk 0 < 16
#pragma unroll
        for (int p = 0; p < 2; p++) {
            const int r = ar0 + 64 * p;
            float4 v = *reinterpret_cast<const float4*>(
                Asrc + (size_t)(bm + r) * DIM + aseg * 4);
            *reinterpret_cast<float4*>(sm_dyn + r * APADW + aseg * 4) = v;
        }
#pragma unroll
        for (int p = 0; p < 2; p++) {
            const int k = bk0 + 16 * p;
            float4 v = *reinterpret_cast<const float4*>(
                Wc + (size_t)k * DIM + bn + bn4);
            *reinterpret_cast<float4*>(sm_dyn + AFLOATS + k * BPADW + bn4) = v;
        }
    }
    __syncthreads();

    for (int c = 0; c < NCHUNK; c++) {
        const int s = c & 1;
        float4 pa[2], pb[2];
        const bool more = (c + 1 < NCHUNK);
        if (more) {   // prefetch chunk c+1 into registers
            const int cn = c + 1;
            const float* Asrc = (cn < 16) ? g_c : x;
            const int koff = (cn < 16) ? cn * KC : cn * KC - 512;
#pragma unroll
            for (int p = 0; p < 2; p++) {
                const int r = ar0 + 64 * p;
                pa[p] = *reinterpret_cast<const float4*>(
                    Asrc + (size_t)(bm + r) * DIM + koff + aseg * 4);
            }
#pragma unroll
            for (int p = 0; p < 2; p++) {
                const int k = bk0 + 16 * p;
                pb[p] = *reinterpret_cast<const float4*>(
                    Wc + (size_t)(cn * KC + k) * DIM + bn + bn4);
            }
        }

        // ---- compute on stage s ----
        const float* As = sm_dyn + s * STAGEF;
        const float* Bs = sm_dyn + s * STAGEF + AFLOATS;
        const uint32_t* Asu = reinterpret_cast<const uint32_t*>(As);
        const uint32_t* Bsu = reinterpret_cast<const uint32_t*>(Bs);
#pragma unroll
        for (int kk = 0; kk < KC; kk += 8) {
            uint32_t a[2][4], bfr[4][2];
#pragma unroll
            for (int ma = 0; ma < 2; ma++) {
                const int r = wm * 32 + ma * 16 + gid;
                a[ma][0] = Asu[r * APADW + kk + tig];
                a[ma][1] = Asu[(r + 8) * APADW + kk + tig];
                a[ma][2] = Asu[r * APADW + kk + tig + 4];
                a[ma][3] = Asu[(r + 8) * APADW + kk + tig + 4];
            }
#pragma unroll
            for (int na = 0; na < 4; na++) {
                const int n = wn * 32 + na * 8 + gid;
                bfr[na][0] = Bsu[(kk + tig) * BPADW + n];
                bfr[na][1] = Bsu[(kk + tig + 4) * BPADW + n];
            }
#pragma unroll
            for (int ma = 0; ma < 2; ma++)
#pragma unroll
                for (int na = 0; na < 4; na++)
                    mma_tf32(acc[ma][na], a[ma][0], a[ma][1], a[ma][2], a[ma][3],
                             bfr[na][0], bfr[na][1]);
        }

        if (more) {   // store prefetched chunk into the other stage
            float* Ad = sm_dyn + (s ^ 1) * STAGEF;
            float* Bd = Ad + AFLOATS;
#pragma unroll
            for (int p = 0; p < 2; p++) {
                const int r = ar0 + 64 * p;
                *reinterpret_cast<float4*>(Ad + r * APADW + aseg * 4) = pa[p];
            }
#pragma unroll
            for (int p = 0; p < 2; p++) {
                const int k = bk0 + 16 * p;
                *reinterpret_cast<float4*>(Bd + k * BPADW + bn4) = pb[p];
            }
            __syncthreads();
        }
    }

    // ---- epilogue: sigmoid + store ----
#pragma unroll
    for (int ma = 0; ma < 2; ma++) {
#pragma unroll
        for (int na = 0; na < 4; na++) {
            const int row = bm + wm * 32 + ma * 16 + gid;
            const int col = bn + wn * 32 + na * 8 + 2 * tig;
            float2 v0, v1;
            v0.x = 1.f / (1.f + __expf(-acc[ma][na][0]));
            v0.y = 1.f / (1.f + __expf(-acc[ma][na][1]));
            v1.x = 1.f / (1.f + __expf(-acc[ma][na][2]));
            v1.y = 1.f / (1.f + __expf(-acc[ma][na][3]));
            *reinterpret_cast<float2*>(out + (size_t)row * DIM + col) = v0;
            *reinterpret_cast<float2*>(out + (size_t)(row + 8) * DIM + col) = v1;
        }
    }
}

extern "C" void kernel_launch(void* const* d_in, const int* in_sizes, int n_in,
                              void* d_out, int out_size) {
    const float* x  = (const float*)d_in[0];   // (4, 2048, 512) fp32
    const float* Wc = (const float*)d_in[1];   // (1024, 512) fp32
    float* out = (float*)d_out;                // (4, 2048, 512) fp32

    const size_t attn_smem = (size_t)(TROWS * TPAD + QT * APAD) * sizeof(float); // 33,280 B
    attn_kernel<<<BATCH * (SEQ / QT), 256, attn_smem>>>(x);

    const size_t gemm_smem = (size_t)(2 * STAGEF) * sizeof(float);  // 70,656 B
    cudaFuncSetAttribute(gemm_mma, cudaFuncAttributeMaxDynamicSharedMemorySize,
                         (int)gemm_smem);
    dim3 grid(DIM / GN, (BATCH * SEQ) / GM);   // (4, 64)
    gemm_mma<<<grid, 512, gemm_smem>>>(x, Wc, out);
}

// round 6
// speedup vs baseline: 3.3782x; 1.9423x over previous
#include <cuda_runtime.h>
#include <cstdint>
#include <math.h>

// ---------------- problem constants ----------------
#define BATCH 4
#define SEQ   2048
#define DIM   512
#define WIN   64
#define QT    32

// attention smem layout
#define TP 516                 // tile row pitch (floats): 516%32=4 -> conflict-free strided row loads
#define SROWS 96
#define SP 100                 // score row pitch

// gemm tiling (mma.sync tf32 m16n8k8)
#define GM 128
#define GN 128
#define KC 32
#define NCHUNK (1024 / KC)     // 32
#define APADW 36
#define BPADW 136              // 136%32=8 -> b-frag banks 8*tig+gid all distinct
#define AFL (GM * APADW)       // 4608
#define BFL (KC * BPADW)       // 4352
#define STF (AFL + BFL)        // 8960 floats per stage
#define NSTAGE 3

// context scratch [B*S, D] fp32 (no cudaMalloc allowed)
__device__ float g_c[BATCH * SEQ * DIM];

__device__ __forceinline__ uint32_t smem_u32(const void* p) {
    uint32_t a;
    asm("{ .reg .u64 t; cvta.to.shared.u64 t, %1; cvt.u32.u64 %0, t; }"
        : "=r"(a) : "l"(p));
    return a;
}
__device__ __forceinline__ void cpa16(uint32_t d, const float* s) {
    asm volatile("cp.async.cg.shared.global [%0], [%1], 16;" :: "r"(d), "l"(s));
}

extern __shared__ float sm_dyn[];

// ---------------------------------------------------------------------------
// Attention: 256 CTAs, 256 threads, QT=32 queries each.
// Whole window tile (96 rows x 512) resident in SMEM; dense-band formulation.
// Window = strictly-causal left 64; zero-padded head rows score exactly 0 and
// are included in the softmax (matches reference).
// ---------------------------------------------------------------------------
__global__ __launch_bounds__(256) void attn_kernel(const float* __restrict__ x) {
    float* tile = sm_dyn;                 // [96][TP]
    float* S    = sm_dyn + SROWS * TP;    // [32][SP]  scores -> band alphas

    const int tid = threadIdx.x;
    const int b   = blockIdx.x >> 6;
    const int qs  = (blockIdx.x & 63) * QT;
    const float* xb = x + (size_t)b * SEQ * DIM;

    // ---- load window tile: rows qs-64 .. qs+31, zero before sequence start ----
#pragma unroll 8
    for (int p = 0; p < 48; p++) {
        const int idx = tid + 256 * p;
        const int r   = idx >> 7;
        const int c4  = (idx & 127) << 2;
        const int gr  = qs - WIN + r;
        float4 v = make_float4(0.f, 0.f, 0.f, 0.f);
        if (gr >= 0)
            v = *reinterpret_cast<const float4*>(xb + (size_t)gr * DIM + c4);
        *reinterpret_cast<float4*>(tile + r * TP + c4) = v;
    }
    __syncthreads();

    const int ty = tid >> 5;     // warp id (i-group of 4)
    const int tx = tid & 31;     // lane

    // ---- phase 1: dense S[i][j] = <tile[64+i], tile[j]>, 4x3 per thread ----
    {
        float sa[4][3];
#pragma unroll
        for (int i = 0; i < 4; i++)
#pragma unroll
            for (int j = 0; j < 3; j++) sa[i][j] = 0.f;

        const float* q0 = tile + (WIN + 4 * ty) * TP;
        const float* k0 = tile + tx * TP;
#pragma unroll 2
        for (int d = 0; d < DIM; d += 4) {
            float4 q[4], k[3];
#pragma unroll
            for (int ii = 0; ii < 4; ii++)
                q[ii] = *reinterpret_cast<const float4*>(q0 + ii * TP + d);
#pragma unroll
            for (int jj = 0; jj < 3; jj++)
                k[jj] = *reinterpret_cast<const float4*>(k0 + jj * 32 * TP + d);
#pragma unroll
            for (int ii = 0; ii < 4; ii++)
#pragma unroll
                for (int jj = 0; jj < 3; jj++) {
                    sa[ii][jj] = fmaf(q[ii].x, k[jj].x, sa[ii][jj]);
                    sa[ii][jj] = fmaf(q[ii].y, k[jj].y, sa[ii][jj]);
                    sa[ii][jj] = fmaf(q[ii].z, k[jj].z, sa[ii][jj]);
                    sa[ii][jj] = fmaf(q[ii].w, k[jj].w, sa[ii][jj]);
                }
        }
#pragma unroll
        for (int ii = 0; ii < 4; ii++)
#pragma unroll
            for (int jj = 0; jj < 3; jj++)
                S[(4 * ty + ii) * SP + tx + 32 * jj] = sa[ii][jj];
    }
    __syncthreads();

    // ---- phase 2: band softmax, in-place -> dense alpha with zeros outside ----
    {
        const int i = tid >> 3;       // row (warp owns 4 full rows)
        const int g = tid & 7;        // 8 lanes per row
        float* srow = S + i * SP;
        float m = -1e30f;
        float vals[8];
#pragma unroll
        for (int w8 = 0; w8 < 8; w8++) {
            vals[w8] = srow[i + g + 8 * w8];   // j = i + w, w in [0,64)
            m = fmaxf(m, vals[w8]);
        }
        m = fmaxf(m, __shfl_xor_sync(0xffffffffu, m, 1));
        m = fmaxf(m, __shfl_xor_sync(0xffffffffu, m, 2));
        m = fmaxf(m, __shfl_xor_sync(0xffffffffu, m, 4));
        float s = 0.f;
#pragma unroll
        for (int w8 = 0; w8 < 8; w8++) s += __expf(vals[w8] - m);
        s += __shfl_xor_sync(0xffffffffu, s, 1);
        s += __shfl_xor_sync(0xffffffffu, s, 2);
        s += __shfl_xor_sync(0xffffffffu, s, 4);
        const float inv = 1.f / s;
        __syncwarp();
#pragma unroll
        for (int jj = 0; jj < 12; jj++) {
            const int j = g * 12 + jj;
            float v = 0.f;
            if (j >= i && j < i + WIN) v = __expf(srow[j] - m) * inv;
            srow[j] = v;
        }
    }
    __syncthreads();

    // ---- phase 3: context c[i][d] = sum_j A[i][j] * tile[j][d], 4x16 per thread ----
    {
        float cacc[4][16];
#pragma unroll
        for (int i = 0; i < 4; i++)
#pragma unroll
            for (int d = 0; d < 16; d++) cacc[i][d] = 0.f;

        const float* arow = S + 4 * ty * SP;
        // band rows for queries 4ty..4ty+3: j in [4ty, 4ty+67]
        for (int j = 0; j < 68; j++) {
            const int jj = 4 * ty + j;
            float a[4];
#pragma unroll
            for (int ii = 0; ii < 4; ii++) a[ii] = arow[ii * SP + jj];
            const float* kr = tile + jj * TP + 4 * tx;
#pragma unroll
            for (int q = 0; q < 4; q++) {
                float4 kv = *reinterpret_cast<const float4*>(kr + 128 * q);
#pragma unroll
                for (int ii = 0; ii < 4; ii++) {
                    cacc[ii][4 * q + 0] = fmaf(a[ii], kv.x, cacc[ii][4 * q + 0]);
                    cacc[ii][4 * q + 1] = fmaf(a[ii], kv.y, cacc[ii][4 * q + 1]);
                    cacc[ii][4 * q + 2] = fmaf(a[ii], kv.z, cacc[ii][4 * q + 2]);
                    cacc[ii][4 * q + 3] = fmaf(a[ii], kv.w, cacc[ii][4 * q + 3]);
                }
            }
        }
#pragma unroll
        for (int ii = 0; ii < 4; ii++) {
            float* crow = g_c + ((size_t)b * SEQ + qs + 4 * ty + ii) * DIM + 4 * tx;
#pragma unroll
            for (int q = 0; q < 4; q++) {
                float4 v = make_float4(cacc[ii][4 * q], cacc[ii][4 * q + 1],
                                       cacc[ii][4 * q + 2], cacc[ii][4 * q + 3]);
                *reinterpret_cast<float4*>(crow + 128 * q) = v;
            }
        }
    }
}

// ---------------------------------------------------------------------------
// Output head: out = sigmoid([c | x] @ Wc) via mma.sync tf32 m16n8k8.
// CTA 128x128, 256 threads, warp tile 64x32, 3-stage cp.async pipeline.
// ---------------------------------------------------------------------------
__device__ __forceinline__ void mma_tf32(float* c, uint32_t a0, uint32_t a1,
                                         uint32_t a2, uint32_t a3,
                                         uint32_t b0, uint32_t b1) {
    asm volatile(
        "mma.sync.aligned.m16n8k8.row.col.f32.tf32.tf32.f32 "
        "{%0,%1,%2,%3}, {%4,%5,%6,%7}, {%8,%9}, {%0,%1,%2,%3};"
        : "+f"(c[0]), "+f"(c[1]), "+f"(c[2]), "+f"(c[3])
        : "r"(a0), "r"(a1), "r"(a2), "r"(a3), "r"(b0), "r"(b1));
}

__device__ __forceinline__ void issue_chunk(int c, int bm, int bn, int tid,
                                            const float* __restrict__ x,
                                            const float* __restrict__ Wc) {
    float* Ad = sm_dyn + (c % NSTAGE) * STF;
    float* Bd = Ad + AFL;
    const float* Asrc = (c < 16) ? g_c : x;
    const int koff = (c < 16) ? c * KC : c * KC - 512;
    // A tile: 128 rows x 32 floats = 1024 x 16B  (FIX: p<4, was p<2 -> rows 64..127 missing)
#pragma unroll
    for (int p = 0; p < 4; p++) {
        const int idx = tid + 256 * p;
        const int r   = idx >> 3;
        const int seg = (idx & 7) * 4;
        cpa16(smem_u32(Ad + r * APADW + seg),
              Asrc + (size_t)(bm + r) * DIM + koff + seg);
    }
    // B tile: 32 rows x 128 floats = 1024 x 16B
#pragma unroll
    for (int p = 0; p < 4; p++) {
        const int idx = tid + 256 * p;
        const int k   = idx >> 5;
        const int n4  = (idx & 31) * 4;
        cpa16(smem_u32(Bd + k * BPADW + n4),
              Wc + (size_t)(c * KC + k) * DIM + bn + n4);
    }
    asm volatile("cp.async.commit_group;" ::: "memory");
}

__global__ __launch_bounds__(256, 2) void gemm_mma(const float* __restrict__ x,
                                                   const float* __restrict__ Wc,
                                                   float* __restrict__ out) {
    const int tid  = threadIdx.x;
    const int wid  = tid >> 5;
    const int lane = tid & 31;
    const int gid  = lane >> 2;
    const int tig  = lane & 3;
    const int wm   = wid & 1;        // 0..1 (64 rows each)
    const int wn   = wid >> 1;       // 0..3 (32 cols each)
    const int bm   = blockIdx.y * GM;
    const int bn   = blockIdx.x * GN;

    float acc[4][4][4];
#pragma unroll
    for (int i = 0; i < 4; i++)
#pragma unroll
        for (int j = 0; j < 4; j++)
#pragma unroll
            for (int k = 0; k < 4; k++) acc[i][j][k] = 0.f;

    issue_chunk(0, bm, bn, tid, x, Wc);
    issue_chunk(1, bm, bn, tid, x, Wc);

    for (int c = 0; c < NCHUNK; c++) {
        if (c == NCHUNK - 1)
            asm volatile("cp.async.wait_group 0;" ::: "memory");
        else
            asm volatile("cp.async.wait_group 1;" ::: "memory");
        __syncthreads();
        if (c + 2 < NCHUNK) issue_chunk(c + 2, bm, bn, tid, x, Wc);

        const uint32_t* Asu = reinterpret_cast<const uint32_t*>(
            sm_dyn + (c % NSTAGE) * STF);
        const uint32_t* Bsu = Asu + AFL;
#pragma unroll
        for (int kk = 0; kk < KC; kk += 8) {
            uint32_t a[4][4], bfr[4][2];
#pragma unroll
            for (int ma = 0; ma < 4; ma++) {
                const int r = wm * 64 + ma * 16 + gid;
                a[ma][0] = Asu[r * APADW + kk + tig];
                a[ma][1] = Asu[(r + 8) * APADW + kk + tig];
                a[ma][2] = Asu[r * APADW + kk + 4 + tig];
                a[ma][3] = Asu[(r + 8) * APADW + kk + 4 + tig];
            }
#pragma unroll
            for (int na = 0; na < 4; na++) {
                const int n = wn * 32 + na * 8 + gid;
                bfr[na][0] = Bsu[(kk + tig) * BPADW + n];
                bfr[na][1] = Bsu[(kk + tig + 4) * BPADW + n];
            }
#pragma unroll
            for (int ma = 0; ma < 4; ma++)
#pragma unroll
                for (int na = 0; na < 4; na++)
                    mma_tf32(acc[ma][na], a[ma][0], a[ma][1], a[ma][2], a[ma][3],
                             bfr[na][0], bfr[na][1]);
        }
    }

    // ---- epilogue: sigmoid + store ----
#pragma unroll
    for (int ma = 0; ma < 4; ma++) {
#pragma unroll
        for (int na = 0; na < 4; na++) {
            const int row = bm + wm * 64 + ma * 16 + gid;
            const int col = bn + wn * 32 + na * 8 + 2 * tig;
            float2 v0, v1;
            v0.x = 1.f / (1.f + __expf(-acc[ma][na][0]));
            v0.y = 1.f / (1.f + __expf(-acc[ma][na][1]));
            v1.x = 1.f / (1.f + __expf(-acc[ma][na][2]));
            v1.y = 1.f / (1.f + __expf(-acc[ma][na][3]));
            *reinterpret_cast<float2*>(out + (size_t)row * DIM + col) = v0;
            *reinterpret_cast<float2*>(out + (size_t)(row + 8) * DIM + col) = v1;
        }
    }
}

extern "C" void kernel_launch(void* const* d_in, const int* in_sizes, int n_in,
                              void* d_out, int out_size) {
    const float* x  = (const float*)d_in[0];   // (4, 2048, 512) fp32
    const float* Wc = (const float*)d_in[1];   // (1024, 512) fp32
    float* out = (float*)d_out;                // (4, 2048, 512) fp32

    const size_t attn_smem = (size_t)(SROWS * TP + QT * SP) * sizeof(float); // 210,944 B
    cudaFuncSetAttribute(attn_kernel, cudaFuncAttributeMaxDynamicSharedMemorySize,
                         (int)attn_smem);
    attn_kernel<<<BATCH * (SEQ / QT), 256, attn_smem>>>(x);

    const size_t gemm_smem = (size_t)(NSTAGE * STF) * sizeof(float);  // 107,520 B
    cudaFuncSetAttribute(gemm_mma, cudaFuncAttributeMaxDynamicSharedMemorySize,
                         (int)gemm_smem);
    dim3 grid(DIM / GN, (BATCH * SEQ) / GM);   // (4, 64)
    gemm_mma<<<grid, 256, gemm_smem>>>(x, Wc, out);
}